// round 1
// baseline (speedup 1.0000x reference)
#include <cuda_runtime.h>
#include <math.h>

#define NTOK 8192
#define DDIM 2048
#define NEXP 8

#define BM 128
#define BN 128
#define BK 16

// Per-expert routing buckets (scratch must be __device__ globals — no allocs allowed)
__device__ int   g_cnt[NEXP];
__device__ int   g_tok[NEXP][NTOK];
__device__ float g_wgt[NEXP][NTOK];

// ---------------------------------------------------------------------------
// Kernel 0: reset per-expert counters
// ---------------------------------------------------------------------------
__global__ void reset_kernel() {
    if (threadIdx.x < NEXP) g_cnt[threadIdx.x] = 0;
}

// ---------------------------------------------------------------------------
// Kernel 1: gating. One warp per token: logits = x @ Wg  (8 dots of 2048),
// top-2 (first-index tie break, matching jax.lax.top_k), softmax over 2,
// atomic append to expert buckets.
// ---------------------------------------------------------------------------
__global__ __launch_bounds__(256) void gate_kernel(const float* __restrict__ x,
                                                   const float* __restrict__ Wg) {
    const int warp = threadIdx.x >> 5;
    const int lane = threadIdx.x & 31;
    const int t = blockIdx.x * 8 + warp;
    if (t >= NTOK) return;

    const float* row = x + (size_t)t * DDIM;
    float acc[8];
#pragma unroll
    for (int e = 0; e < 8; ++e) acc[e] = 0.f;

    for (int i = lane; i < DDIM; i += 32) {
        float xv = row[i];
        const float4* w4 = reinterpret_cast<const float4*>(Wg + (size_t)i * 8);
        float4 a = w4[0];
        float4 b = w4[1];
        acc[0] += xv * a.x;  acc[1] += xv * a.y;
        acc[2] += xv * a.z;  acc[3] += xv * a.w;
        acc[4] += xv * b.x;  acc[5] += xv * b.y;
        acc[6] += xv * b.z;  acc[7] += xv * b.w;
    }
#pragma unroll
    for (int off = 16; off > 0; off >>= 1) {
#pragma unroll
        for (int e = 0; e < 8; ++e)
            acc[e] += __shfl_xor_sync(0xffffffffu, acc[e], off);
    }

    if (lane == 0) {
        int i0 = 0; float v0 = acc[0];
#pragma unroll
        for (int e = 1; e < 8; ++e)
            if (acc[e] > v0) { v0 = acc[e]; i0 = e; }
        int i1 = -1; float v1 = -INFINITY;
#pragma unroll
        for (int e = 0; e < 8; ++e)
            if (e != i0 && acc[e] > v1) { v1 = acc[e]; i1 = e; }

        float ew = expf(v1 - v0);           // <= 1
        float inv = 1.f / (1.f + ew);
        float w0 = inv;
        float w1 = ew * inv;

        int p0 = atomicAdd(&g_cnt[i0], 1);
        g_tok[i0][p0] = t;  g_wgt[i0][p0] = w0;
        int p1 = atomicAdd(&g_cnt[i1], 1);
        g_tok[i1][p1] = t;  g_wgt[i1][p1] = w1;
    }
}

// ---------------------------------------------------------------------------
// Kernel 2: gathered expert GEMM. Block = 128x128 output tile of one expert's
// bucket. Double-buffered smem, 8x8 per-thread microtile (256 threads).
// Epilogue: atomicAdd(out[token], w * (acc + bias)).
// ---------------------------------------------------------------------------
__global__ __launch_bounds__(256, 2) void expert_gemm(const float* __restrict__ X,
                                                      const float* __restrict__ We,
                                                      const float* __restrict__ be,
                                                      float* __restrict__ out) {
    const int e = blockIdx.z;
    const int cnt = g_cnt[e];
    const int m0 = blockIdx.y * BM;
    if (m0 >= cnt) return;
    const int n0 = blockIdx.x * BN;

    __shared__ float As[2][BK][BM + 4];   // padded, transposed A (k-major)
    __shared__ float Bs[2][BK][BN];
    __shared__ int   s_tok[BM];
    __shared__ float s_w[BM];

    const int tid = threadIdx.x;

    if (tid < BM) {
        int r = m0 + tid;
        if (r < cnt) { s_tok[tid] = g_tok[e][r]; s_w[tid] = g_wgt[e][r]; }
        else         { s_tok[tid] = g_tok[e][cnt - 1]; s_w[tid] = 0.f; }
    }
    __syncthreads();

    // A-load mapping: 4 float4 per row (BK=16), 64 rows/pass, 2 passes
    const int ar = tid >> 2;          // 0..63
    const int ak = (tid & 3) * 4;     // 0,4,8,12
    // B-load mapping: 32 float4 per k-row, 8 rows/pass, 2 passes
    const int br = tid >> 5;          // 0..7
    const int bn = (tid & 31) * 4;    // 0..124

    const float* Be = We + (size_t)e * DDIM * DDIM;

    const int r0 = s_tok[ar];
    const int r1 = s_tok[ar + 64];

    float4 pa0, pa1, pb0, pb1;

    // prologue: tile 0 -> buffer 0
    pa0 = *reinterpret_cast<const float4*>(X + (size_t)r0 * DDIM + ak);
    pa1 = *reinterpret_cast<const float4*>(X + (size_t)r1 * DDIM + ak);
    pb0 = *reinterpret_cast<const float4*>(Be + (size_t)br * DDIM + n0 + bn);
    pb1 = *reinterpret_cast<const float4*>(Be + (size_t)(br + 8) * DDIM + n0 + bn);

    As[0][ak + 0][ar] = pa0.x; As[0][ak + 1][ar] = pa0.y;
    As[0][ak + 2][ar] = pa0.z; As[0][ak + 3][ar] = pa0.w;
    As[0][ak + 0][ar + 64] = pa1.x; As[0][ak + 1][ar + 64] = pa1.y;
    As[0][ak + 2][ar + 64] = pa1.z; As[0][ak + 3][ar + 64] = pa1.w;
    *reinterpret_cast<float4*>(&Bs[0][br][bn]) = pb0;
    *reinterpret_cast<float4*>(&Bs[0][br + 8][bn]) = pb1;
    __syncthreads();

    const int ty = tid >> 4;   // 0..15  -> rows ty*8..ty*8+7
    const int tx = tid & 15;   // 0..15  -> cols tx*8..tx*8+7

    float accv[8][8];
#pragma unroll
    for (int i = 0; i < 8; ++i)
#pragma unroll
        for (int j = 0; j < 8; ++j) accv[i][j] = 0.f;

    const int NT = DDIM / BK;   // 128
    int buf = 0;

    for (int kt = 0; kt < NT; ++kt) {
        const bool has_next = (kt + 1 < NT);
        if (has_next) {
            const int k0 = (kt + 1) * BK;
            pa0 = *reinterpret_cast<const float4*>(X + (size_t)r0 * DDIM + k0 + ak);
            pa1 = *reinterpret_cast<const float4*>(X + (size_t)r1 * DDIM + k0 + ak);
            pb0 = *reinterpret_cast<const float4*>(Be + (size_t)(k0 + br) * DDIM + n0 + bn);
            pb1 = *reinterpret_cast<const float4*>(Be + (size_t)(k0 + br + 8) * DDIM + n0 + bn);
        }

#pragma unroll
        for (int kk = 0; kk < BK; ++kk) {
            float4 a0 = *reinterpret_cast<const float4*>(&As[buf][kk][ty * 8]);
            float4 a1 = *reinterpret_cast<const float4*>(&As[buf][kk][ty * 8 + 4]);
            float4 b0 = *reinterpret_cast<const float4*>(&Bs[buf][kk][tx * 8]);
            float4 b1 = *reinterpret_cast<const float4*>(&Bs[buf][kk][tx * 8 + 4]);
            float af[8] = {a0.x, a0.y, a0.z, a0.w, a1.x, a1.y, a1.z, a1.w};
            float bf[8] = {b0.x, b0.y, b0.z, b0.w, b1.x, b1.y, b1.z, b1.w};
#pragma unroll
            for (int i = 0; i < 8; ++i)
#pragma unroll
                for (int j = 0; j < 8; ++j)
                    accv[i][j] = fmaf(af[i], bf[j], accv[i][j]);
        }

        if (has_next) {
            const int nb = buf ^ 1;
            As[nb][ak + 0][ar] = pa0.x; As[nb][ak + 1][ar] = pa0.y;
            As[nb][ak + 2][ar] = pa0.z; As[nb][ak + 3][ar] = pa0.w;
            As[nb][ak + 0][ar + 64] = pa1.x; As[nb][ak + 1][ar + 64] = pa1.y;
            As[nb][ak + 2][ar + 64] = pa1.z; As[nb][ak + 3][ar + 64] = pa1.w;
            *reinterpret_cast<float4*>(&Bs[nb][br][bn]) = pb0;
            *reinterpret_cast<float4*>(&Bs[nb][br + 8][bn]) = pb1;
            __syncthreads();
            buf = nb;
        }
    }

    // epilogue: out[token, n0+tx*8 .. +7] += w * (acc + bias)
    float bias[8];
#pragma unroll
    for (int j = 0; j < 8; ++j)
        bias[j] = be[(size_t)e * DDIM + n0 + tx * 8 + j];

#pragma unroll
    for (int i = 0; i < 8; ++i) {
        const int mi = ty * 8 + i;
        const float w = s_w[mi];
        if (w != 0.f) {
            float* orow = out + (size_t)s_tok[mi] * DDIM + n0 + tx * 8;
#pragma unroll
            for (int j = 0; j < 8; ++j)
                atomicAdd(orow + j, w * (accv[i][j] + bias[j]));
        }
    }
}

// ---------------------------------------------------------------------------
extern "C" void kernel_launch(void* const* d_in, const int* in_sizes, int n_in,
                              void* d_out, int out_size) {
    const float* x  = (const float*)d_in[0];
    const float* Wg = (const float*)d_in[1];
    const float* We = (const float*)d_in[2];
    const float* be = (const float*)d_in[3];
    float* out = (float*)d_out;

    reset_kernel<<<1, 32>>>();
    gate_kernel<<<NTOK / 8, 256>>>(x, Wg);
    cudaMemsetAsync(d_out, 0, (size_t)out_size * sizeof(float), 0);

    dim3 grid(DDIM / BN, NTOK / BM, NEXP);
    expert_gemm<<<grid, 256>>>(x, We, be, out);
}

// round 3
// speedup vs baseline: 3.0602x; 3.0602x over previous
#include <cuda_runtime.h>
#include <math.h>
#include <stdint.h>

#define NTOK 8192
#define DDIM 2048
#define NEXP 8

#define BM 128
#define BN 128
#define BK 32
#define KTILES (DDIM / BK)     // 64

// smem geometry (floats)
#define AS_STRIDE 36           // 32 + 4 pad  -> conflict-free A frag reads
#define BS_STRIDE 136          // 128 + 8 pad -> conflict-free B frag reads
#define AS_FLOATS (BM * AS_STRIDE)              // 4608
#define BS_FLOATS (BK * BS_STRIDE)              // 4352
#define OFF_B0    (2 * AS_FLOATS)               // 9216
#define OFF_TOK   (OFF_B0 + 2 * BS_FLOATS)      // 17920
#define OFF_W     (OFF_TOK + BM)                // 18048
#define SMEM_FLOATS (OFF_W + BM)                // 18176
#define SMEM_BYTES  (SMEM_FLOATS * 4)           // 72704

// ---------------------------------------------------------------------------
// Scratch (device globals: allocations are forbidden)
// ---------------------------------------------------------------------------
__device__ int   g_cnt[NEXP];
__device__ int   g_tok[NEXP][NTOK];     // packed: token*2 + slot
__device__ float g_wgt[NEXP][NTOK];
__device__ float g_Xc[(size_t)NTOK * DDIM];             // tf32-rounded X
__device__ float g_Wc[(size_t)NEXP * DDIM * DDIM];      // tf32-rounded We
__device__ float g_slot[(size_t)2 * NTOK * DDIM];       // weighted per-slot outputs

// ---------------------------------------------------------------------------
__device__ __forceinline__ float to_tf32(float x) {
    float r;
    asm("cvt.rna.tf32.f32 %0, %1;" : "=f"(r) : "f"(x));
    return r;
}
__device__ __forceinline__ uint32_t smem_u32(const void* p) {
    uint32_t a;
    asm("{ .reg .u64 t; cvta.to.shared.u64 t, %1; cvt.u32.u64 %0, t; }" : "=r"(a) : "l"(p));
    return a;
}
#define CP16(dst, src) \
    asm volatile("cp.async.cg.shared.global [%0], [%1], 16;" :: "r"(dst), "l"(src) : "memory")
#define CP_COMMIT() asm volatile("cp.async.commit_group;" ::: "memory")
#define CP_WAIT1()  asm volatile("cp.async.wait_group 1;" ::: "memory")

__device__ __forceinline__ void mma_tf32(float& c0, float& c1, float& c2, float& c3,
                                         float a0, float a1, float a2, float a3,
                                         float b0, float b1) {
    asm volatile(
        "mma.sync.aligned.m16n8k8.row.col.f32.tf32.tf32.f32 "
        "{%0,%1,%2,%3}, {%4,%5,%6,%7}, {%8,%9}, {%0,%1,%2,%3};"
        : "+f"(c0), "+f"(c1), "+f"(c2), "+f"(c3)
        : "r"(__float_as_uint(a0)), "r"(__float_as_uint(a1)),
          "r"(__float_as_uint(a2)), "r"(__float_as_uint(a3)),
          "r"(__float_as_uint(b0)), "r"(__float_as_uint(b1)));
}

// ---------------------------------------------------------------------------
__global__ void reset_kernel() {
    if (threadIdx.x < NEXP) g_cnt[threadIdx.x] = 0;
}

// gating: one warp per token
__global__ __launch_bounds__(256) void gate_kernel(const float* __restrict__ x,
                                                   const float* __restrict__ Wg) {
    const int warp = threadIdx.x >> 5;
    const int lane = threadIdx.x & 31;
    const int t = blockIdx.x * 8 + warp;
    if (t >= NTOK) return;

    const float* row = x + (size_t)t * DDIM;
    float acc[8];
#pragma unroll
    for (int e = 0; e < 8; ++e) acc[e] = 0.f;

    for (int i = lane; i < DDIM; i += 32) {
        float xv = row[i];
        const float4* w4 = reinterpret_cast<const float4*>(Wg + (size_t)i * 8);
        float4 a = w4[0], b = w4[1];
        acc[0] += xv * a.x;  acc[1] += xv * a.y;
        acc[2] += xv * a.z;  acc[3] += xv * a.w;
        acc[4] += xv * b.x;  acc[5] += xv * b.y;
        acc[6] += xv * b.z;  acc[7] += xv * b.w;
    }
#pragma unroll
    for (int off = 16; off > 0; off >>= 1)
#pragma unroll
        for (int e = 0; e < 8; ++e)
            acc[e] += __shfl_xor_sync(0xffffffffu, acc[e], off);

    if (lane == 0) {
        int i0 = 0; float v0 = acc[0];
#pragma unroll
        for (int e = 1; e < 8; ++e)
            if (acc[e] > v0) { v0 = acc[e]; i0 = e; }
        int i1 = -1; float v1 = -INFINITY;
#pragma unroll
        for (int e = 0; e < 8; ++e)
            if (e != i0 && acc[e] > v1) { v1 = acc[e]; i1 = e; }

        float ew = expf(v1 - v0);
        float inv = 1.f / (1.f + ew);
        int p0 = atomicAdd(&g_cnt[i0], 1);
        g_tok[i0][p0] = t * 2;      g_wgt[i0][p0] = inv;
        int p1 = atomicAdd(&g_cnt[i1], 1);
        g_tok[i1][p1] = t * 2 + 1;  g_wgt[i1][p1] = ew * inv;
    }
}

// elementwise f32 -> tf32(rna) copy
__global__ __launch_bounds__(256) void conv_tf32(const float* __restrict__ src,
                                                 float* __restrict__ dst, int n4) {
    int i = blockIdx.x * 256 + threadIdx.x;
    int stride = gridDim.x * 256;
    const float4* s4 = reinterpret_cast<const float4*>(src);
    float4* d4 = reinterpret_cast<float4*>(dst);
    for (; i < n4; i += stride) {
        float4 v = s4[i];
        v.x = to_tf32(v.x); v.y = to_tf32(v.y);
        v.z = to_tf32(v.z); v.w = to_tf32(v.w);
        d4[i] = v;
    }
}

// ---------------------------------------------------------------------------
// TF32 mma.sync gathered expert GEMM. CTA = 128x128, 8 warps (2M x 4N),
// warp tile 64x32, double-buffered cp.async (BK=32).
// ---------------------------------------------------------------------------
__global__ __launch_bounds__(256, 2) void expert_gemm(const float* __restrict__ be) {
    const int e = blockIdx.z;
    const int cnt = g_cnt[e];
    const int m0 = blockIdx.y * BM;
    if (m0 >= cnt) return;
    const int n0 = blockIdx.x * BN;

    extern __shared__ float smem[];
    int*   s_tok = reinterpret_cast<int*>(smem + OFF_TOK);
    float* s_w   = smem + OFF_W;

    const int tid = threadIdx.x;
    const int lane = tid & 31;
    const int wid = tid >> 5;
    const int warp_m = wid >> 2;   // 0..1
    const int warp_n = wid & 3;    // 0..3
    const int lr = lane >> 2;      // 0..7
    const int lc = lane & 3;       // 0..3

    if (tid < BM) {
        int r = m0 + tid;
        if (r < cnt) { s_tok[tid] = g_tok[e][r]; s_w[tid] = g_wgt[e][r]; }
        else         { s_tok[tid] = -1;          s_w[tid] = 0.f; }
    }
    __syncthreads();

    const uint32_t sbase = smem_u32(smem);

    // --- per-thread cp.async mappings (constant across k-tiles) ---
    // A: 1024 16B chunks: row = idx>>3 (8 chunks/row), kc = idx&7
    const float* a_src[4];
    uint32_t a_off[4];
#pragma unroll
    for (int i = 0; i < 4; ++i) {
        int idx = tid + i * 256;
        int row = idx >> 3, kc = idx & 7;
        int t2 = s_tok[row];
        int token = (t2 < 0 ? 0 : t2) >> 1;
        a_src[i] = g_Xc + (size_t)token * DDIM + kc * 4;
        a_off[i] = (uint32_t)(row * AS_STRIDE + kc * 4) * 4;
    }
    // B: 1024 chunks: k = idx>>5, nc = idx&31
    const float* b_src[4];
    uint32_t b_off[4];
    const float* Wbase = g_Wc + (size_t)e * DDIM * DDIM + n0;
#pragma unroll
    for (int i = 0; i < 4; ++i) {
        int idx = tid + i * 256;
        int k = idx >> 5, nc = idx & 31;
        b_src[i] = Wbase + (size_t)k * DDIM + nc * 4;
        b_off[i] = (uint32_t)(OFF_B0 + k * BS_STRIDE + nc * 4) * 4;
    }

    // --- prologue: stage tiles 0 and 1 ---
#pragma unroll
    for (int s = 0; s < 2; ++s) {
#pragma unroll
        for (int i = 0; i < 4; ++i)
            CP16(sbase + s * (AS_FLOATS * 4) + a_off[i], a_src[i] + s * BK);
#pragma unroll
        for (int i = 0; i < 4; ++i)
            CP16(sbase + s * (BS_FLOATS * 4) + b_off[i], b_src[i] + (size_t)s * BK * DDIM);
        CP_COMMIT();
    }
    CP_WAIT1();
    __syncthreads();

    float c[4][4][4];
#pragma unroll
    for (int mi = 0; mi < 4; ++mi)
#pragma unroll
        for (int ni = 0; ni < 4; ++ni)
#pragma unroll
            for (int j = 0; j < 4; ++j) c[mi][ni][j] = 0.f;

    const int ar0 = warp_m * 64 + lr;
    const int bc0 = warp_n * 32 + lr;

    for (int kt = 0; kt < KTILES; ++kt) {
        const int s = kt & 1;
        const float* As = smem + s * AS_FLOATS;
        const float* Bs = smem + OFF_B0 + s * BS_FLOATS;

#pragma unroll
        for (int ks = 0; ks < 4; ++ks) {
            const int k0 = ks * 8;
            float av[4][4];
#pragma unroll
            for (int mi = 0; mi < 4; ++mi) {
                const float* ap = As + (ar0 + mi * 16) * AS_STRIDE + k0 + lc;
                av[mi][0] = ap[0];
                av[mi][1] = ap[8 * AS_STRIDE];
                av[mi][2] = ap[4];
                av[mi][3] = ap[8 * AS_STRIDE + 4];
            }
            float bv[4][2];
#pragma unroll
            for (int ni = 0; ni < 4; ++ni) {
                const float* bp = Bs + (k0 + lc) * BS_STRIDE + bc0 + ni * 8;
                bv[ni][0] = bp[0];
                bv[ni][1] = bp[4 * BS_STRIDE];
            }
#pragma unroll
            for (int mi = 0; mi < 4; ++mi)
#pragma unroll
                for (int ni = 0; ni < 4; ++ni)
                    mma_tf32(c[mi][ni][0], c[mi][ni][1], c[mi][ni][2], c[mi][ni][3],
                             av[mi][0], av[mi][1], av[mi][2], av[mi][3],
                             bv[ni][0], bv[ni][1]);
        }

        __syncthreads();
        if (kt + 2 < KTILES) {
            const int nk = kt + 2;
#pragma unroll
            for (int i = 0; i < 4; ++i)
                CP16(sbase + s * (AS_FLOATS * 4) + a_off[i], a_src[i] + nk * BK);
#pragma unroll
            for (int i = 0; i < 4; ++i)
                CP16(sbase + s * (BS_FLOATS * 4) + b_off[i], b_src[i] + (size_t)nk * BK * DDIM);
        }
        CP_COMMIT();
        CP_WAIT1();
        __syncthreads();
    }

    // --- epilogue: weighted (+bias) rows -> slot buffer, STG.64 ---
    const float* brow = be + (size_t)e * DDIM + n0;
#pragma unroll
    for (int mi = 0; mi < 4; ++mi) {
        const int r0 = warp_m * 64 + mi * 16 + lr;
        const int r1 = r0 + 8;
        const int t20 = s_tok[r0];
        const int t21 = s_tok[r1];
        const float w0 = s_w[r0];
        const float w1 = s_w[r1];
        float* dst0 = g_slot + (size_t)(t20 < 0 ? 0 : t20) * DDIM + n0;
        float* dst1 = g_slot + (size_t)(t21 < 0 ? 0 : t21) * DDIM + n0;
#pragma unroll
        for (int ni = 0; ni < 4; ++ni) {
            const int col = warp_n * 32 + ni * 8 + 2 * lc;
            const float bb0 = __ldg(brow + col);
            const float bb1 = __ldg(brow + col + 1);
            if (t20 >= 0) {
                float2 v = make_float2(w0 * (c[mi][ni][0] + bb0),
                                       w0 * (c[mi][ni][1] + bb1));
                *reinterpret_cast<float2*>(dst0 + col) = v;
            }
            if (t21 >= 0) {
                float2 v = make_float2(w1 * (c[mi][ni][2] + bb0),
                                       w1 * (c[mi][ni][3] + bb1));
                *reinterpret_cast<float2*>(dst1 + col) = v;
            }
        }
    }
}

// combine: out[t] = slot[2t] + slot[2t+1]
__global__ __launch_bounds__(256) void combine_kernel(float* __restrict__ out) {
    const int D4 = DDIM / 4;                // 512
    int i = blockIdx.x * 256 + threadIdx.x; // over N*D/4
    const float4* s4 = reinterpret_cast<const float4*>(g_slot);
    float4* o4 = reinterpret_cast<float4*>(out);
    if (i < NTOK * D4) {
        int t = i / D4, d = i - t * D4;
        float4 a = s4[(size_t)(2 * t) * D4 + d];
        float4 b = s4[(size_t)(2 * t + 1) * D4 + d];
        o4[i] = make_float4(a.x + b.x, a.y + b.y, a.z + b.z, a.w + b.w);
    }
}

// ---------------------------------------------------------------------------
extern "C" void kernel_launch(void* const* d_in, const int* in_sizes, int n_in,
                              void* d_out, int out_size) {
    const float* x  = (const float*)d_in[0];
    const float* Wg = (const float*)d_in[1];
    const float* We = (const float*)d_in[2];
    const float* be = (const float*)d_in[3];
    float* out = (float*)d_out;

    cudaFuncSetAttribute(expert_gemm, cudaFuncAttributeMaxDynamicSharedMemorySize, SMEM_BYTES);

    reset_kernel<<<1, 32>>>();
    gate_kernel<<<NTOK / 8, 256>>>(x, Wg);

    float* xc; cudaGetSymbolAddress((void**)&xc, g_Xc);
    float* wc; cudaGetSymbolAddress((void**)&wc, g_Wc);
    conv_tf32<<<2048, 256>>>(x, xc, NTOK * DDIM / 4);
    conv_tf32<<<4096, 256>>>(We, wc, NEXP * DDIM * DDIM / 4);

    dim3 grid(DDIM / BN, NTOK / BM, NEXP);
    expert_gemm<<<grid, 256, SMEM_BYTES>>>(be);

    combine_kernel<<<(NTOK * DDIM / 4 + 255) / 256, 256>>>(out);
}

// round 4
// speedup vs baseline: 3.2451x; 1.0604x over previous
#include <cuda_runtime.h>
#include <math.h>
#include <stdint.h>

#define NTOK 8192
#define DDIM 2048
#define NEXP 8

#define BM 128
#define BN 256
#define BK 32
#define KTILES (DDIM / BK)     // 64

// smem geometry (floats)
#define AS_STRIDE 36                       // 32 + 4 pad
#define BS_STRIDE 264                      // 256 + 8 pad
#define AS_FLOATS (BM * AS_STRIDE)         // 4608
#define BS_FLOATS (BK * BS_STRIDE)         // 8448
#define OFF_B0    (3 * AS_FLOATS)          // 13824
#define OFF_TOK   (OFF_B0 + 3 * BS_FLOATS) // 39168
#define OFF_W     (OFF_TOK + BM)           // 39296
#define SMEM_FLOATS (OFF_W + BM)           // 39424
#define SMEM_BYTES  (SMEM_FLOATS * 4)      // 157696

// ---------------------------------------------------------------------------
// Scratch (device globals: allocations are forbidden)
// ---------------------------------------------------------------------------
__device__ int   g_cnt[NEXP];
__device__ int   g_tok[NEXP][NTOK];     // packed: token*2 + slot
__device__ float g_wgt[NEXP][NTOK];
__device__ float g_Xc[(size_t)NTOK * DDIM];        // tf32(RNA)-rounded X
__device__ float g_slot[(size_t)2 * NTOK * DDIM];  // weighted per-slot outputs

// ---------------------------------------------------------------------------
__device__ __forceinline__ float to_tf32(float x) {
    float r;
    asm("cvt.rna.tf32.f32 %0, %1;" : "=f"(r) : "f"(x));
    return r;
}
__device__ __forceinline__ uint32_t smem_u32(const void* p) {
    uint32_t a;
    asm("{ .reg .u64 t; cvta.to.shared.u64 t, %1; cvt.u32.u64 %0, t; }" : "=r"(a) : "l"(p));
    return a;
}
#define CP16(dst, src) \
    asm volatile("cp.async.cg.shared.global [%0], [%1], 16;" :: "r"(dst), "l"(src) : "memory")
#define CP_COMMIT() asm volatile("cp.async.commit_group;" ::: "memory")
#define CP_WAIT1()  asm volatile("cp.async.wait_group 1;" ::: "memory")

__device__ __forceinline__ void mma_tf32(float& c0, float& c1, float& c2, float& c3,
                                         float a0, float a1, float a2, float a3,
                                         float b0, float b1) {
    asm volatile(
        "mma.sync.aligned.m16n8k8.row.col.f32.tf32.tf32.f32 "
        "{%0,%1,%2,%3}, {%4,%5,%6,%7}, {%8,%9}, {%0,%1,%2,%3};"
        : "+f"(c0), "+f"(c1), "+f"(c2), "+f"(c3)
        : "r"(__float_as_uint(a0)), "r"(__float_as_uint(a1)),
          "r"(__float_as_uint(a2)), "r"(__float_as_uint(a3)),
          "r"(__float_as_uint(b0)), "r"(__float_as_uint(b1)));
}

// ---------------------------------------------------------------------------
__global__ void reset_kernel() {
    if (threadIdx.x < NEXP) g_cnt[threadIdx.x] = 0;
}

// gating: one warp per token
__global__ __launch_bounds__(256) void gate_kernel(const float* __restrict__ x,
                                                   const float* __restrict__ Wg) {
    const int warp = threadIdx.x >> 5;
    const int lane = threadIdx.x & 31;
    const int t = blockIdx.x * 8 + warp;
    if (t >= NTOK) return;

    const float* row = x + (size_t)t * DDIM;
    float acc[8];
#pragma unroll
    for (int e = 0; e < 8; ++e) acc[e] = 0.f;

    for (int i = lane; i < DDIM; i += 32) {
        float xv = row[i];
        const float4* w4 = reinterpret_cast<const float4*>(Wg + (size_t)i * 8);
        float4 a = w4[0], b = w4[1];
        acc[0] += xv * a.x;  acc[1] += xv * a.y;
        acc[2] += xv * a.z;  acc[3] += xv * a.w;
        acc[4] += xv * b.x;  acc[5] += xv * b.y;
        acc[6] += xv * b.z;  acc[7] += xv * b.w;
    }
#pragma unroll
    for (int off = 16; off > 0; off >>= 1)
#pragma unroll
        for (int e = 0; e < 8; ++e)
            acc[e] += __shfl_xor_sync(0xffffffffu, acc[e], off);

    if (lane == 0) {
        int i0 = 0; float v0 = acc[0];
#pragma unroll
        for (int e = 1; e < 8; ++e)
            if (acc[e] > v0) { v0 = acc[e]; i0 = e; }
        int i1 = -1; float v1 = -INFINITY;
#pragma unroll
        for (int e = 0; e < 8; ++e)
            if (e != i0 && acc[e] > v1) { v1 = acc[e]; i1 = e; }

        float ew = expf(v1 - v0);
        float inv = 1.f / (1.f + ew);
        int p0 = atomicAdd(&g_cnt[i0], 1);
        g_tok[i0][p0] = t * 2;      g_wgt[i0][p0] = inv;
        int p1 = atomicAdd(&g_cnt[i1], 1);
        g_tok[i1][p1] = t * 2 + 1;  g_wgt[i1][p1] = ew * inv;
    }
}

// elementwise f32 -> tf32(rna) copy (X only)
__global__ __launch_bounds__(256) void conv_tf32(const float* __restrict__ src,
                                                 float* __restrict__ dst, int n4) {
    int i = blockIdx.x * 256 + threadIdx.x;
    int stride = gridDim.x * 256;
    const float4* s4 = reinterpret_cast<const float4*>(src);
    float4* d4 = reinterpret_cast<float4*>(dst);
    for (; i < n4; i += stride) {
        float4 v = s4[i];
        v.x = to_tf32(v.x); v.y = to_tf32(v.y);
        v.z = to_tf32(v.z); v.w = to_tf32(v.w);
        d4[i] = v;
    }
}

// ---------------------------------------------------------------------------
// TF32 mma.sync gathered expert GEMM. CTA = 128x256, 8 warps (2M x 4N),
// warp tile 64x64, 3-stage cp.async, one barrier per k-tile.
// B (We) is consumed raw fp32 -> HW tf32 truncation (unbiased noise).
// ---------------------------------------------------------------------------
__global__ __launch_bounds__(256, 1) void expert_gemm(const float* __restrict__ We,
                                                      const float* __restrict__ be) {
    const int e = blockIdx.z;
    const int cnt = g_cnt[e];
    const int m0 = blockIdx.y * BM;
    if (m0 >= cnt) return;
    const int n0 = blockIdx.x * BN;

    extern __shared__ float smem[];
    int*   s_tok = reinterpret_cast<int*>(smem + OFF_TOK);
    float* s_w   = smem + OFF_W;

    const int tid = threadIdx.x;
    const int lane = tid & 31;
    const int wid = tid >> 5;
    const int warp_m = wid >> 2;   // 0..1
    const int warp_n = wid & 3;    // 0..3
    const int lr = lane >> 2;      // 0..7
    const int lc = lane & 3;       // 0..3

    if (tid < BM) {
        int r = m0 + tid;
        if (r < cnt) { s_tok[tid] = g_tok[e][r]; s_w[tid] = g_wgt[e][r]; }
        else         { s_tok[tid] = -1;          s_w[tid] = 0.f; }
    }
    __syncthreads();

    const uint32_t sbase = smem_u32(smem);

    // A: 1024 16B chunks/tile: row = idx>>3, kc = idx&7   (4 per thread)
    const float* a_src[4];
    uint32_t a_off[4];
#pragma unroll
    for (int i = 0; i < 4; ++i) {
        int idx = tid + i * 256;
        int row = idx >> 3, kc = idx & 7;
        int t2 = s_tok[row];
        int token = (t2 < 0 ? 0 : t2) >> 1;
        a_src[i] = g_Xc + (size_t)token * DDIM + kc * 4;
        a_off[i] = (uint32_t)(row * AS_STRIDE + kc * 4) * 4;
    }
    // B: 2048 chunks/tile: k = idx>>6, nc = idx&63        (8 per thread)
    const float* b_src[8];
    uint32_t b_off[8];
    const float* Wbase = We + (size_t)e * DDIM * DDIM + n0;
#pragma unroll
    for (int i = 0; i < 8; ++i) {
        int idx = tid + i * 256;
        int k = idx >> 6, nc = idx & 63;
        b_src[i] = Wbase + (size_t)k * DDIM + nc * 4;
        b_off[i] = (uint32_t)(OFF_B0 + k * BS_STRIDE + nc * 4) * 4;
    }

    // --- prologue: stage tiles 0 and 1 ---
#pragma unroll
    for (int s = 0; s < 2; ++s) {
#pragma unroll
        for (int i = 0; i < 4; ++i)
            CP16(sbase + s * (AS_FLOATS * 4) + a_off[i], a_src[i] + s * BK);
#pragma unroll
        for (int i = 0; i < 8; ++i)
            CP16(sbase + s * (BS_FLOATS * 4) + b_off[i], b_src[i] + (size_t)s * BK * DDIM);
        CP_COMMIT();
    }

    float c[4][8][4];
#pragma unroll
    for (int mi = 0; mi < 4; ++mi)
#pragma unroll
        for (int ni = 0; ni < 8; ++ni)
#pragma unroll
            for (int j = 0; j < 4; ++j) c[mi][ni][j] = 0.f;

    const int ar0 = warp_m * 64 + lr;
    const int bc0 = warp_n * 64 + lr;

    for (int kt = 0; kt < KTILES; ++kt) {
        CP_WAIT1();                 // stage kt resident
        __syncthreads();            // all stage-(kt-1) reads done, kt visible

        // refill buffer (kt+2)%3
        if (kt + 2 < KTILES) {
            const int sw = (kt + 2) % 3;
            const int nk = kt + 2;
#pragma unroll
            for (int i = 0; i < 4; ++i)
                CP16(sbase + sw * (AS_FLOATS * 4) + a_off[i], a_src[i] + nk * BK);
#pragma unroll
            for (int i = 0; i < 8; ++i)
                CP16(sbase + sw * (BS_FLOATS * 4) + b_off[i], b_src[i] + (size_t)nk * BK * DDIM);
        }
        CP_COMMIT();

        const int s = kt % 3;
        const float* As = smem + s * AS_FLOATS;
        const float* Bs = smem + OFF_B0 + s * BS_FLOATS;

#pragma unroll
        for (int ks = 0; ks < 4; ++ks) {
            const int k0 = ks * 8;
            float av[4][4];
#pragma unroll
            for (int mi = 0; mi < 4; ++mi) {
                const float* ap = As + (ar0 + mi * 16) * AS_STRIDE + k0 + lc;
                av[mi][0] = ap[0];
                av[mi][1] = ap[8 * AS_STRIDE];
                av[mi][2] = ap[4];
                av[mi][3] = ap[8 * AS_STRIDE + 4];
            }
            float bv[8][2];
#pragma unroll
            for (int ni = 0; ni < 8; ++ni) {
                const float* bp = Bs + (k0 + lc) * BS_STRIDE + bc0 + ni * 8;
                bv[ni][0] = bp[0];
                bv[ni][1] = bp[4 * BS_STRIDE];
            }
#pragma unroll
            for (int mi = 0; mi < 4; ++mi)
#pragma unroll
                for (int ni = 0; ni < 8; ++ni)
                    mma_tf32(c[mi][ni][0], c[mi][ni][1], c[mi][ni][2], c[mi][ni][3],
                             av[mi][0], av[mi][1], av[mi][2], av[mi][3],
                             bv[ni][0], bv[ni][1]);
        }
    }

    // --- epilogue: weighted (+bias) rows -> slot buffer ---
    const float* brow = be + (size_t)e * DDIM + n0;
#pragma unroll
    for (int mi = 0; mi < 4; ++mi) {
        const int r0 = warp_m * 64 + mi * 16 + lr;
        const int r1 = r0 + 8;
        const int t20 = s_tok[r0];
        const int t21 = s_tok[r1];
        const float w0 = s_w[r0];
        const float w1 = s_w[r1];
        float* dst0 = g_slot + (size_t)(t20 < 0 ? 0 : t20) * DDIM + n0;
        float* dst1 = g_slot + (size_t)(t21 < 0 ? 0 : t21) * DDIM + n0;
#pragma unroll
        for (int ni = 0; ni < 8; ++ni) {
            const int col = warp_n * 64 + ni * 8 + 2 * lc;
            const float bb0 = __ldg(brow + col);
            const float bb1 = __ldg(brow + col + 1);
            if (t20 >= 0) {
                float2 v = make_float2(w0 * (c[mi][ni][0] + bb0),
                                       w0 * (c[mi][ni][1] + bb1));
                *reinterpret_cast<float2*>(dst0 + col) = v;
            }
            if (t21 >= 0) {
                float2 v = make_float2(w1 * (c[mi][ni][2] + bb0),
                                       w1 * (c[mi][ni][3] + bb1));
                *reinterpret_cast<float2*>(dst1 + col) = v;
            }
        }
    }
}

// combine: out[t] = slot[2t] + slot[2t+1]
__global__ __launch_bounds__(256) void combine_kernel(float* __restrict__ out) {
    const int D4 = DDIM / 4;                // 512
    int i = blockIdx.x * 256 + threadIdx.x; // over N*D/4
    const float4* s4 = reinterpret_cast<const float4*>(g_slot);
    float4* o4 = reinterpret_cast<float4*>(out);
    if (i < NTOK * D4) {
        int t = i / D4, d = i - t * D4;
        float4 a = s4[(size_t)(2 * t) * D4 + d];
        float4 b = s4[(size_t)(2 * t + 1) * D4 + d];
        o4[i] = make_float4(a.x + b.x, a.y + b.y, a.z + b.z, a.w + b.w);
    }
}

// ---------------------------------------------------------------------------
extern "C" void kernel_launch(void* const* d_in, const int* in_sizes, int n_in,
                              void* d_out, int out_size) {
    const float* x  = (const float*)d_in[0];
    const float* Wg = (const float*)d_in[1];
    const float* We = (const float*)d_in[2];
    const float* be = (const float*)d_in[3];
    float* out = (float*)d_out;

    cudaFuncSetAttribute(expert_gemm, cudaFuncAttributeMaxDynamicSharedMemorySize, SMEM_BYTES);

    reset_kernel<<<1, 32>>>();
    gate_kernel<<<NTOK / 8, 256>>>(x, Wg);

    float* xc; cudaGetSymbolAddress((void**)&xc, g_Xc);
    conv_tf32<<<2048, 256>>>(x, xc, NTOK * DDIM / 4);

    dim3 grid(DDIM / BN, NTOK / BM, NEXP);
    expert_gemm<<<grid, 256, SMEM_BYTES>>>(We, be);

    combine_kernel<<<(NTOK * DDIM / 4 + 255) / 256, 256>>>(out);
}

// round 5
// speedup vs baseline: 3.2668x; 1.0067x over previous
#include <cuda_runtime.h>
#include <math.h>
#include <stdint.h>

#define NTOK 8192
#define DDIM 2048
#define NEXP 8

#define BM 128
#define BN 256
#define BK 32
#define KTILES (DDIM / BK)     // 64

// smem geometry (floats)
#define AS_STRIDE 36                       // 32 + 4 pad
#define BS_STRIDE 264                      // 256 + 8 pad
#define AS_FLOATS (BM * AS_STRIDE)         // 4608
#define BS_FLOATS (BK * BS_STRIDE)         // 8448
#define OFF_B0    (3 * AS_FLOATS)          // 13824
#define OFF_TOK   (OFF_B0 + 3 * BS_FLOATS) // 39168
#define OFF_W     (OFF_TOK + BM)           // 39296
#define SMEM_FLOATS (OFF_W + BM)           // 39424
#define SMEM_BYTES  (SMEM_FLOATS * 4)      // 157696

// ---------------------------------------------------------------------------
__device__ int   g_cnt[NEXP];
__device__ int   g_tok[NEXP][NTOK];     // packed: token*2 + slot
__device__ float g_wgt[NEXP][NTOK];
__device__ float g_Xc[(size_t)NTOK * DDIM];        // tf32(RNA)-rounded X
__device__ float g_slot[(size_t)2 * NTOK * DDIM];  // weighted per-slot outputs

// ---------------------------------------------------------------------------
__device__ __forceinline__ float to_tf32(float x) {
    float r;
    asm("cvt.rna.tf32.f32 %0, %1;" : "=f"(r) : "f"(x));
    return r;
}
__device__ __forceinline__ uint32_t smem_u32(const void* p) {
    uint32_t a;
    asm("{ .reg .u64 t; cvta.to.shared.u64 t, %1; cvt.u32.u64 %0, t; }" : "=r"(a) : "l"(p));
    return a;
}
#define CP16(dst, src) \
    asm volatile("cp.async.cg.shared.global [%0], [%1], 16;" :: "r"(dst), "l"(src) : "memory")
#define CP_COMMIT() asm volatile("cp.async.commit_group;" ::: "memory")
#define CP_WAIT1()  asm volatile("cp.async.wait_group 1;" ::: "memory")

__device__ __forceinline__ void mma_tf32(float& c0, float& c1, float& c2, float& c3,
                                         float a0, float a1, float a2, float a3,
                                         float b0, float b1) {
    asm volatile(
        "mma.sync.aligned.m16n8k8.row.col.f32.tf32.tf32.f32 "
        "{%0,%1,%2,%3}, {%4,%5,%6,%7}, {%8,%9}, {%0,%1,%2,%3};"
        : "+f"(c0), "+f"(c1), "+f"(c2), "+f"(c3)
        : "r"(__float_as_uint(a0)), "r"(__float_as_uint(a1)),
          "r"(__float_as_uint(a2)), "r"(__float_as_uint(a3)),
          "r"(__float_as_uint(b0)), "r"(__float_as_uint(b1)));
}

// ---------------------------------------------------------------------------
__global__ void reset_kernel() {
    if (threadIdx.x < NEXP) g_cnt[threadIdx.x] = 0;
}

// gating: one warp per token
__global__ __launch_bounds__(256) void gate_kernel(const float* __restrict__ x,
                                                   const float* __restrict__ Wg) {
    const int warp = threadIdx.x >> 5;
    const int lane = threadIdx.x & 31;
    const int t = blockIdx.x * 8 + warp;
    if (t >= NTOK) return;

    const float* row = x + (size_t)t * DDIM;
    float acc[8];
#pragma unroll
    for (int e = 0; e < 8; ++e) acc[e] = 0.f;

    for (int i = lane; i < DDIM; i += 32) {
        float xv = row[i];
        const float4* w4 = reinterpret_cast<const float4*>(Wg + (size_t)i * 8);
        float4 a = w4[0], b = w4[1];
        acc[0] += xv * a.x;  acc[1] += xv * a.y;
        acc[2] += xv * a.z;  acc[3] += xv * a.w;
        acc[4] += xv * b.x;  acc[5] += xv * b.y;
        acc[6] += xv * b.z;  acc[7] += xv * b.w;
    }
#pragma unroll
    for (int off = 16; off > 0; off >>= 1)
#pragma unroll
        for (int e = 0; e < 8; ++e)
            acc[e] += __shfl_xor_sync(0xffffffffu, acc[e], off);

    if (lane == 0) {
        int i0 = 0; float v0 = acc[0];
#pragma unroll
        for (int e = 1; e < 8; ++e)
            if (acc[e] > v0) { v0 = acc[e]; i0 = e; }
        int i1 = -1; float v1 = -INFINITY;
#pragma unroll
        for (int e = 0; e < 8; ++e)
            if (e != i0 && acc[e] > v1) { v1 = acc[e]; i1 = e; }

        float ew = expf(v1 - v0);
        float inv = 1.f / (1.f + ew);
        int p0 = atomicAdd(&g_cnt[i0], 1);
        g_tok[i0][p0] = t * 2;      g_wgt[i0][p0] = inv;
        int p1 = atomicAdd(&g_cnt[i1], 1);
        g_tok[i1][p1] = t * 2 + 1;  g_wgt[i1][p1] = ew * inv;
    }
}

// elementwise f32 -> tf32(rna) copy (X only)
__global__ __launch_bounds__(256) void conv_tf32(const float* __restrict__ src,
                                                 float* __restrict__ dst, int n4) {
    int i = blockIdx.x * 256 + threadIdx.x;
    int stride = gridDim.x * 256;
    const float4* s4 = reinterpret_cast<const float4*>(src);
    float4* d4 = reinterpret_cast<float4*>(dst);
    for (; i < n4; i += stride) {
        float4 v = s4[i];
        v.x = to_tf32(v.x); v.y = to_tf32(v.y);
        v.z = to_tf32(v.z); v.w = to_tf32(v.w);
        d4[i] = v;
    }
}

// ---------------------------------------------------------------------------
// TF32 mma.sync gathered expert GEMM. CTA = 128x256, 8 warps (2M x 4N),
// warp tile 64x64, 3-stage cp.async, register-fragment double buffering.
// ---------------------------------------------------------------------------
__global__ __launch_bounds__(256, 1) void expert_gemm(const float* __restrict__ We,
                                                      const float* __restrict__ be) {
    const int e = blockIdx.z;
    const int cnt = g_cnt[e];
    const int m0 = blockIdx.y * BM;
    if (m0 >= cnt) return;
    const int n0 = blockIdx.x * BN;

    extern __shared__ float smem[];
    int*   s_tok = reinterpret_cast<int*>(smem + OFF_TOK);
    float* s_w   = smem + OFF_W;

    const int tid = threadIdx.x;
    const int lane = tid & 31;
    const int wid = tid >> 5;
    const int warp_m = wid >> 2;   // 0..1
    const int warp_n = wid & 3;    // 0..3
    const int lr = lane >> 2;      // 0..7
    const int lc = lane & 3;       // 0..3

    if (tid < BM) {
        int r = m0 + tid;
        if (r < cnt) { s_tok[tid] = g_tok[e][r]; s_w[tid] = g_wgt[e][r]; }
        else         { s_tok[tid] = -1;          s_w[tid] = 0.f; }
    }
    __syncthreads();

    const uint32_t sbase = smem_u32(smem);

    // ---- addressing: u32 global offsets + advancing base pointers ----
    // A: 1024 16B chunks/tile: row = idx>>3, kc = idx&7   (4 per thread)
    uint32_t a_goff[4], a_soff[4];
#pragma unroll
    for (int i = 0; i < 4; ++i) {
        int idx = tid + i * 256;
        int row = idx >> 3, kc = idx & 7;
        int t2 = s_tok[row];
        int token = (t2 < 0 ? 0 : t2) >> 1;
        a_goff[i] = (uint32_t)token * (DDIM * 4) + kc * 16;
        a_soff[i] = (uint32_t)(row * AS_STRIDE + kc * 4) * 4;
    }
    // B: 2048 chunks/tile: k = idx>>6, nc = idx&63        (8 per thread)
    uint32_t b_goff[8], b_soff[8];
#pragma unroll
    for (int i = 0; i < 8; ++i) {
        int idx = tid + i * 256;
        int k = idx >> 6, nc = idx & 63;
        b_goff[i] = (uint32_t)k * (DDIM * 4) + nc * 16;
        b_soff[i] = (uint32_t)(OFF_B0 + k * BS_STRIDE + nc * 4) * 4;
    }
    const char* aBase = reinterpret_cast<const char*>(g_Xc);                      // +kt*BK*4
    const char* bBase = reinterpret_cast<const char*>(We + (size_t)e * DDIM * DDIM + n0); // +kt*BK*DDIM*4

    // --- prologue: stage tiles 0 and 1 ---
#pragma unroll
    for (int s = 0; s < 2; ++s) {
#pragma unroll
        for (int i = 0; i < 4; ++i)
            CP16(sbase + s * (AS_FLOATS * 4) + a_soff[i], aBase + a_goff[i] + s * (BK * 4));
#pragma unroll
        for (int i = 0; i < 8; ++i)
            CP16(sbase + s * (BS_FLOATS * 4) + b_soff[i], bBase + b_goff[i] + (size_t)s * (BK * DDIM * 4));
        CP_COMMIT();
    }

    float c[4][8][4];
#pragma unroll
    for (int mi = 0; mi < 4; ++mi)
#pragma unroll
        for (int ni = 0; ni < 8; ++ni)
#pragma unroll
            for (int j = 0; j < 4; ++j) c[mi][ni][j] = 0.f;

    const int ar0 = warp_m * 64 + lr;
    const int bc0 = warp_n * 64 + lr;

    float av[2][4][4];
    float bv[2][8][2];

#define LOAD_FRAGS(buf, As, Bs, ks)                                              \
    do {                                                                         \
        const int _k0 = (ks) * 8;                                                \
        _Pragma("unroll")                                                        \
        for (int mi = 0; mi < 4; ++mi) {                                         \
            const float* ap = (As) + (ar0 + mi * 16) * AS_STRIDE + _k0 + lc;     \
            av[buf][mi][0] = ap[0];                                              \
            av[buf][mi][1] = ap[8 * AS_STRIDE];                                  \
            av[buf][mi][2] = ap[4];                                              \
            av[buf][mi][3] = ap[8 * AS_STRIDE + 4];                              \
        }                                                                        \
        _Pragma("unroll")                                                        \
        for (int ni = 0; ni < 8; ++ni) {                                         \
            const float* bp = (Bs) + (_k0 + lc) * BS_STRIDE + bc0 + ni * 8;      \
            bv[buf][ni][0] = bp[0];                                              \
            bv[buf][ni][1] = bp[4 * BS_STRIDE];                                  \
        }                                                                        \
    } while (0)

#pragma unroll 1
    for (int kt = 0; kt < KTILES; ++kt) {
        CP_WAIT1();                 // stage kt resident
        __syncthreads();            // stage-(kt-1) reads done, kt visible

        // refill buffer (kt+2)%3
        if (kt + 2 < KTILES) {
            const int sw = (kt + 2) % 3;
            const int nk = kt + 2;
#pragma unroll
            for (int i = 0; i < 4; ++i)
                CP16(sbase + sw * (AS_FLOATS * 4) + a_soff[i], aBase + a_goff[i] + nk * (BK * 4));
#pragma unroll
            for (int i = 0; i < 8; ++i)
                CP16(sbase + sw * (BS_FLOATS * 4) + b_soff[i], bBase + b_goff[i] + (size_t)nk * (BK * DDIM * 4));
        }
        CP_COMMIT();

        const int s = kt % 3;
        const float* As = smem + s * AS_FLOATS;
        const float* Bs = smem + OFF_B0 + s * BS_FLOATS;

        LOAD_FRAGS(0, As, Bs, 0);
#pragma unroll
        for (int ks = 0; ks < 4; ++ks) {
            const int cur = ks & 1;
            if (ks < 3) LOAD_FRAGS(cur ^ 1, As, Bs, ks + 1);
#pragma unroll
            for (int mi = 0; mi < 4; ++mi)
#pragma unroll
                for (int ni = 0; ni < 8; ++ni)
                    mma_tf32(c[mi][ni][0], c[mi][ni][1], c[mi][ni][2], c[mi][ni][3],
                             av[cur][mi][0], av[cur][mi][1], av[cur][mi][2], av[cur][mi][3],
                             bv[cur][ni][0], bv[cur][ni][1]);
        }
    }

    // --- epilogue: weighted (+bias) rows -> slot buffer ---
    const float* brow = be + (size_t)e * DDIM + n0;
#pragma unroll
    for (int mi = 0; mi < 4; ++mi) {
        const int r0 = warp_m * 64 + mi * 16 + lr;
        const int r1 = r0 + 8;
        const int t20 = s_tok[r0];
        const int t21 = s_tok[r1];
        const float w0 = s_w[r0];
        const float w1 = s_w[r1];
        float* dst0 = g_slot + (size_t)(t20 < 0 ? 0 : t20) * DDIM + n0;
        float* dst1 = g_slot + (size_t)(t21 < 0 ? 0 : t21) * DDIM + n0;
#pragma unroll
        for (int ni = 0; ni < 8; ++ni) {
            const int col = warp_n * 64 + ni * 8 + 2 * lc;
            const float bb0 = __ldg(brow + col);
            const float bb1 = __ldg(brow + col + 1);
            if (t20 >= 0) {
                float2 v = make_float2(w0 * (c[mi][ni][0] + bb0),
                                       w0 * (c[mi][ni][1] + bb1));
                *reinterpret_cast<float2*>(dst0 + col) = v;
            }
            if (t21 >= 0) {
                float2 v = make_float2(w1 * (c[mi][ni][2] + bb0),
                                       w1 * (c[mi][ni][3] + bb1));
                *reinterpret_cast<float2*>(dst1 + col) = v;
            }
        }
    }
}

// combine: out[t] = slot[2t] + slot[2t+1]
__global__ __launch_bounds__(256) void combine_kernel(float* __restrict__ out) {
    const int D4 = DDIM / 4;                // 512
    int i = blockIdx.x * 256 + threadIdx.x; // over N*D/4
    const float4* s4 = reinterpret_cast<const float4*>(g_slot);
    float4* o4 = reinterpret_cast<float4*>(out);
    if (i < NTOK * D4) {
        int t = i / D4, d = i - t * D4;
        float4 a = s4[(size_t)(2 * t) * D4 + d];
        float4 b = s4[(size_t)(2 * t + 1) * D4 + d];
        o4[i] = make_float4(a.x + b.x, a.y + b.y, a.z + b.z, a.w + b.w);
    }
}

// ---------------------------------------------------------------------------
extern "C" void kernel_launch(void* const* d_in, const int* in_sizes, int n_in,
                              void* d_out, int out_size) {
    const float* x  = (const float*)d_in[0];
    const float* Wg = (const float*)d_in[1];
    const float* We = (const float*)d_in[2];
    const float* be = (const float*)d_in[3];
    float* out = (float*)d_out;

    cudaFuncSetAttribute(expert_gemm, cudaFuncAttributeMaxDynamicSharedMemorySize, SMEM_BYTES);

    reset_kernel<<<1, 32>>>();
    gate_kernel<<<NTOK / 8, 256>>>(x, Wg);

    float* xc; cudaGetSymbolAddress((void**)&xc, g_Xc);
    conv_tf32<<<2048, 256>>>(x, xc, NTOK * DDIM / 4);

    dim3 grid(DDIM / BN, NTOK / BM, NEXP);
    expert_gemm<<<grid, 256, SMEM_BYTES>>>(We, be);

    combine_kernel<<<(NTOK * DDIM / 4 + 255) / 256, 256>>>(out);
}